// round 14
// baseline (speedup 1.0000x reference)
#include <cuda_runtime.h>
#include <math.h>

#define B 16
#define LQ 2048
#define EMB1 1024
#define EMB2 768
#define HDIM 1024
#define NHEAD 16
#define DH 64
#define GRIDX 27      // 27*16 = 432 blocks <= 444 = 148 SMs x 3 -> single wave

// Scratch (static device globals; no allocation in kernel_launch).
__device__ float g_K[B * HDIM];
__device__ float g_V[B * HDIM];
__device__ float g_Weff[B * NHEAD * EMB1];
__device__ float g_c[B * NHEAD];

// Packed f32x2 FMA: acc = a*b + acc elementwise on (lo,hi) float pairs.
__device__ __forceinline__ void fma2(unsigned long long& acc,
                                     unsigned long long a, unsigned long long b) {
    asm("fma.rn.f32x2 %0, %1, %2, %0;" : "+l"(acc) : "l"(a), "l"(b));
}
__device__ __forceinline__ float unpack_sum(unsigned long long a) {
    float lo, hi;
    asm("mov.b64 {%0, %1}, %2;" : "=f"(lo), "=f"(hi) : "l"(a));
    return lo + hi;
}

// ---------------------------------------------------------------------------
// Kernel 1 (proven ~10us): 256 blocks x 512 thr; block stages 4 j-columns of
// both Wk and Wv (24 KB); warp b computes 4 K-dots + 4 V-dots, folded reduce.
// ---------------------------------------------------------------------------
__global__ __launch_bounds__(512, 2) void kv_kernel(const float* __restrict__ emb2,
                          const float* __restrict__ Wk, const float* __restrict__ bk,
                          const float* __restrict__ Wv, const float* __restrict__ bv) {
    __shared__ float4 wk_s[4][EMB2 / 4];   // 12 KB
    __shared__ float4 wv_s[4][EMB2 / 4];   // 12 KB
    int j0 = blockIdx.x * 4;
    int tid = threadIdx.x;

    const float4* Wk4 = (const float4*)(Wk + j0 * EMB2);
    const float4* Wv4 = (const float4*)(Wv + j0 * EMB2);
    for (int t = tid; t < 4 * (EMB2 / 4); t += 512)
        wk_s[t / (EMB2 / 4)][t % (EMB2 / 4)] = __ldg(Wk4 + t);
    for (int t = tid; t < 4 * (EMB2 / 4); t += 512)
        wv_s[t / (EMB2 / 4)][t % (EMB2 / 4)] = __ldg(Wv4 + t);
    __syncthreads();

    int b = tid >> 5, lane = tid & 31;
    const float4* e4 = (const float4*)(emb2 + b * EMB2);

    float4 e[6];
#pragma unroll
    for (int i = 0; i < 6; i++) e[i] = __ldg(&e4[i * 32 + lane]);

    float v[8];                 // v[0..3] = K dots, v[4..7] = V dots
#pragma unroll
    for (int jj = 0; jj < 4; jj++) {
        float ak = 0.f, av = 0.f;
#pragma unroll
        for (int i = 0; i < 6; i++) {
            float4 k = wk_s[jj][i * 32 + lane];
            float4 w = wv_s[jj][i * 32 + lane];
            ak = fmaf(e[i].x, k.x, ak); ak = fmaf(e[i].y, k.y, ak);
            ak = fmaf(e[i].z, k.z, ak); ak = fmaf(e[i].w, k.w, ak);
            av = fmaf(e[i].x, w.x, av); av = fmaf(e[i].y, w.y, av);
            av = fmaf(e[i].z, w.z, av); av = fmaf(e[i].w, w.w, av);
        }
        v[jj] = ak; v[jj + 4] = av;
    }

#pragma unroll
    for (int s = 0; s < 3; s++) {
        int o = 1 << s;
        int bit = (lane >> s) & 1;
#pragma unroll
        for (int j = 0; j < (4 >> s); j++) {
            float keep = bit ? v[2 * j + 1] : v[2 * j];
            float send = bit ? v[2 * j] : v[2 * j + 1];
            v[j] = keep + __shfl_xor_sync(0xffffffffu, send, o);
        }
    }
    v[0] += __shfl_xor_sync(0xffffffffu, v[0], 8);
    v[0] += __shfl_xor_sync(0xffffffffu, v[0], 16);

    if (lane < 4)
        g_K[b * HDIM + j0 + lane] = v[0] + bk[j0 + lane];
    else if (lane < 8)
        g_V[b * HDIM + j0 + lane - 4] = v[0] + bv[j0 + lane - 4];
}

// ---------------------------------------------------------------------------
// Kernel 2 (proven ~4us): Weff[b,h,e] = sum_d Wq[h*64+d,e] * K[b,h*64+d],
// with the c fold on the (0,h,0) blocks.
// ---------------------------------------------------------------------------
__global__ void weff_kernel(const float* __restrict__ Wq, const float* __restrict__ bq) {
    __shared__ float Wq_s[DH * 128];
    __shared__ float Ks[DH];
    int h = blockIdx.y;
    int e0 = blockIdx.x * 128;
    int bg = blockIdx.z;
    int tid = threadIdx.x;

    if (blockIdx.x == 0 && bg == 0 && tid < B) {
        float a = 0.f;
#pragma unroll 16
        for (int d = 0; d < DH; d++)
            a = fmaf(bq[h * DH + d], g_K[tid * HDIM + h * DH + d], a);
        g_c[tid * NHEAD + h] = a;
    }

#pragma unroll 8
    for (int d = 0; d < DH; d++)
        Wq_s[d * 128 + tid] = Wq[(h * DH + d) * EMB1 + e0 + tid];

    for (int bb = 0; bb < 4; bb++) {
        int b = bg * 4 + bb;
        __syncthreads();
        if (tid < DH) Ks[tid] = g_K[b * HDIM + h * DH + tid];
        __syncthreads();
        float a = 0.f;
#pragma unroll 16
        for (int d = 0; d < DH; d++)
            a = fmaf(Wq_s[d * 128 + tid], Ks[d], a);
        g_Weff[(b * NHEAD + h) * EMB1 + e0 + tid] = a;
    }
}

// ---------------------------------------------------------------------------
// Kernel 3 (main): R5 row-pair structure at 192 threads, (192,3) -> 113
// regs/thread (~100 live: NO spills) and 18 warps/SM across 3 independent
// blocks (smem 3 x 69.7 KB = 209 KB < 228 KB). R13 profile showed L1tex 38us
// and DRAM 32us overlapping to only 61us at 16 warps/SM -> latency-bound;
// this raises residency without touching the proven inner loop.
// ---------------------------------------------------------------------------
__global__ __launch_bounds__(192, 3) void main_kernel(const float* __restrict__ emb1,
                                                      float* __restrict__ out) {
    extern __shared__ float sm[];
    float* Weff_s = sm;                    // 16384 floats
    float* V_s = sm + NHEAD * EMB1;        // 1024 floats
    float* c_s = V_s + HDIM;               // 16 floats

    int b = blockIdx.y;
    int tid = threadIdx.x;

    // Cooperative staging of Weff[b], V[b], c[b]
    {
        const float4* Wg = (const float4*)(g_Weff + (size_t)b * NHEAD * EMB1);
        float4* Ws4 = (float4*)Weff_s;
        for (int i = tid; i < NHEAD * EMB1 / 4; i += 192)
            Ws4[i] = Wg[i];
        const float4* Vg = (const float4*)(g_V + (size_t)b * HDIM);
        for (int i = tid; i < HDIM / 4; i += 192)
            ((float4*)V_s)[i] = Vg[i];
        if (tid < NHEAD) c_s[tid] = g_c[b * NHEAD + tid];
    }
    __syncthreads();

    int warp = tid >> 5, lane = tid & 31;
    const ulonglong2* Wsd = (const ulonglong2*)Weff_s;
    const float4* Vs4 = (const float4*)V_s;
    int hi = lane >> 4;
    float c_l = c_s[lane & 15];

    // Row pairs: 1024 per batch over 27 blocks x 6 warps = 162 warps.
    for (int p = blockIdx.x * 6 + warp; p < LQ / 2; p += GRIDX * 6) {
        const ulonglong2* x0p = (const ulonglong2*)(emb1 + ((size_t)b * LQ + 2 * p) * EMB1);
        const ulonglong2* x1p = x0p + EMB1 / 4;

        ulonglong2 x0 = __ldg(x0p + lane);
        ulonglong2 x1 = __ldg(x1p + lane);

        unsigned long long acc0[NHEAD], acc1[NHEAD];
#pragma unroll
        for (int h = 0; h < NHEAD; h++) { acc0[h] = 0ull; acc1[h] = 0ull; }

#pragma unroll
        for (int i = 0; i < 8; i++) {
            ulonglong2 x0n, x1n;
            if (i < 7) {                               // prefetch next chunk
                x0n = __ldg(x0p + (i + 1) * 32 + lane);
                x1n = __ldg(x1p + (i + 1) * 32 + lane);
            }
#pragma unroll
            for (int h = 0; h < NHEAD; h++) {
                ulonglong2 w = Wsd[h * 256 + i * 32 + lane];
                fma2(acc0[h], x0.x, w.x);
                fma2(acc0[h], x0.y, w.y);
                fma2(acc1[h], x1.x, w.x);
                fma2(acc1[h], x1.y, w.y);
            }
            if (i < 7) { x0 = x0n; x1 = x1n; }
        }

        // Unpack f32x2 partials, then folded reduction: lane l -> head (l&15).
        float v0[NHEAD], v1[NHEAD];
#pragma unroll
        for (int h = 0; h < NHEAD; h++) {
            v0[h] = unpack_sum(acc0[h]);
            v1[h] = unpack_sum(acc1[h]);
        }
#pragma unroll
        for (int s = 0; s < 4; s++) {
            int o = 1 << s;
            int bit = (lane >> s) & 1;
#pragma unroll
            for (int j = 0; j < (8 >> s); j++) {
                float k0 = bit ? v0[2 * j + 1] : v0[2 * j];
                float s0 = bit ? v0[2 * j] : v0[2 * j + 1];
                v0[j] = k0 + __shfl_xor_sync(0xffffffffu, s0, o);
                float k1 = bit ? v1[2 * j + 1] : v1[2 * j];
                float s1 = bit ? v1[2 * j] : v1[2 * j + 1];
                v1[j] = k1 + __shfl_xor_sync(0xffffffffu, s1, o);
            }
        }
        v0[0] += __shfl_xor_sync(0xffffffffu, v0[0], 16);
        v1[0] += __shfl_xor_sync(0xffffffffu, v1[0], 16);

        float sig0 = __fdividef(1.f, 1.f + __expf(-(v0[0] + c_l)));
        float sig1 = __fdividef(1.f, 1.f + __expf(-(v1[0] + c_l)));

        float4* o0 = (float4*)(out + ((size_t)b * LQ + 2 * p) * EMB1);
        float4* o1 = o0 + EMB1 / 4;
#pragma unroll
        for (int i = 0; i < 8; i++) {
            // float4 (i*32+lane) belongs to head 2i + hi; lane (2i+hi) holds it.
            float s0 = __shfl_sync(0xffffffffu, sig0, 2 * i + hi);
            float s1 = __shfl_sync(0xffffffffu, sig1, 2 * i + hi);
            float4 v = Vs4[i * 32 + lane];
            float4 r0, r1;
            r0.x = s0 * v.x; r0.y = s0 * v.y; r0.z = s0 * v.z; r0.w = s0 * v.w;
            r1.x = s1 * v.x; r1.y = s1 * v.y; r1.z = s1 * v.z; r1.w = s1 * v.w;
            o0[i * 32 + lane] = r0;
            o1[i * 32 + lane] = r1;
        }
    }
}

// ---------------------------------------------------------------------------
extern "C" void kernel_launch(void* const* d_in, const int* in_sizes, int n_in,
                              void* d_out, int out_size) {
    const float* emb1 = (const float*)d_in[0];
    const float* emb2 = (const float*)d_in[1];
    const float* Wq   = (const float*)d_in[2];
    const float* bq   = (const float*)d_in[3];
    const float* Wk   = (const float*)d_in[4];
    const float* bk   = (const float*)d_in[5];
    const float* Wv   = (const float*)d_in[6];
    const float* bv   = (const float*)d_in[7];
    float* out = (float*)d_out;

    kv_kernel<<<HDIM / 4, 512>>>(emb2, Wk, bk, Wv, bv);
    weff_kernel<<<dim3(EMB1 / 128, NHEAD, 4), 128>>>(Wq, bq);

    int smem = (NHEAD * EMB1 + HDIM + NHEAD) * (int)sizeof(float);  // ~69.7 KB
    static bool attr_set = false;
    if (!attr_set) {
        cudaFuncSetAttribute(main_kernel, cudaFuncAttributeMaxDynamicSharedMemorySize, smem);
        attr_set = true;
    }
    main_kernel<<<dim3(GRIDX, B), 192, smem>>>(emb1, out);
}

// round 15
// speedup vs baseline: 1.1222x; 1.1222x over previous
#include <cuda_runtime.h>
#include <math.h>

#define B 16
#define LQ 2048
#define EMB1 1024
#define EMB2 768
#define HDIM 1024
#define NHEAD 16
#define DH 64
#define GRIDX 18      // main grid (18,16) = 288 blocks = 144 SMs x 2

// Scratch (static device globals; no allocation in kernel_launch).
__device__ float g_K[B * HDIM];
__device__ float g_V[B * HDIM];
__device__ float g_Weff[B * NHEAD * EMB1];
__device__ float g_c[B * NHEAD];

// Packed f32x2 FMA: acc = a*b + acc elementwise on (lo,hi) float pairs.
__device__ __forceinline__ void fma2(unsigned long long& acc,
                                     unsigned long long a, unsigned long long b) {
    asm("fma.rn.f32x2 %0, %1, %2, %0;" : "+l"(acc) : "l"(a), "l"(b));
}
__device__ __forceinline__ float unpack_sum(unsigned long long a) {
    float lo, hi;
    asm("mov.b64 {%0, %1}, %2;" : "=f"(lo), "=f"(hi) : "l"(a));
    return lo + hi;
}

// ---------------------------------------------------------------------------
// Kernel 1 (redesigned for latency): 512 blocks x 256 thr, 4 blocks/SM ->
// single wave. Block stages 2 j-columns of BOTH Wk and Wv (12 KB); warp w
// handles batches {w, w+8}: 4 dots (K/V x 2 j) + folded 4-value reduce.
// ---------------------------------------------------------------------------
__global__ __launch_bounds__(256, 4) void kv_kernel(const float* __restrict__ emb2,
                          const float* __restrict__ Wk, const float* __restrict__ bk,
                          const float* __restrict__ Wv, const float* __restrict__ bv) {
    __shared__ float4 ws[768];     // [0:192) Wk j0 | [192:384) Wk j1
                                   // [384:576) Wv j0 | [576:768) Wv j1
    int j0 = blockIdx.x * 2;
    int tid = threadIdx.x;

    const float4* Wk4 = (const float4*)(Wk + j0 * EMB2);   // 2 rows contiguous
    const float4* Wv4 = (const float4*)(Wv + j0 * EMB2);
    for (int t = tid; t < 384; t += 256) ws[t] = __ldg(Wk4 + t);
    for (int t = tid; t < 384; t += 256) ws[384 + t] = __ldg(Wv4 + t);
    __syncthreads();

    int w = tid >> 5, lane = tid & 31;

#pragma unroll
    for (int bb = 0; bb < 2; bb++) {
        int b = w + bb * 8;
        const float4* e4 = (const float4*)(emb2 + b * EMB2);

        float4 e[6];
#pragma unroll
        for (int i = 0; i < 6; i++) e[i] = __ldg(&e4[i * 32 + lane]);

        float v[4];                // {K j0, K j1, V j0, V j1}
#pragma unroll
        for (int t = 0; t < 4; t++) {
            float a = 0.f;
#pragma unroll
            for (int i = 0; i < 6; i++) {
                float4 q = ws[t * 192 + i * 32 + lane];
                a = fmaf(e[i].x, q.x, a); a = fmaf(e[i].y, q.y, a);
                a = fmaf(e[i].z, q.z, a); a = fmaf(e[i].w, q.w, a);
            }
            v[t] = a;
        }

        // Folded reduce: lane l ends holding total for target (l & 3).
#pragma unroll
        for (int s = 0; s < 2; s++) {
            int o = 1 << s;
            int bit = (lane >> s) & 1;
#pragma unroll
            for (int j = 0; j < (2 >> s); j++) {
                float keep = bit ? v[2 * j + 1] : v[2 * j];
                float send = bit ? v[2 * j] : v[2 * j + 1];
                v[j] = keep + __shfl_xor_sync(0xffffffffu, send, o);
            }
        }
        v[0] += __shfl_xor_sync(0xffffffffu, v[0], 4);
        v[0] += __shfl_xor_sync(0xffffffffu, v[0], 8);
        v[0] += __shfl_xor_sync(0xffffffffu, v[0], 16);

        if (lane < 2)
            g_K[b * HDIM + j0 + lane] = v[0] + bk[j0 + lane];
        else if (lane < 4)
            g_V[b * HDIM + j0 + lane - 2] = v[0] + bv[j0 + lane - 2];
    }
}

// ---------------------------------------------------------------------------
// Kernel 2 (proven ~4us): Weff[b,h,e] = sum_d Wq[h*64+d,e] * K[b,h*64+d],
// with the c fold on the (0,h,0) blocks.
// ---------------------------------------------------------------------------
__global__ void weff_kernel(const float* __restrict__ Wq, const float* __restrict__ bq) {
    __shared__ float Wq_s[DH * 128];
    __shared__ float Ks[DH];
    int h = blockIdx.y;
    int e0 = blockIdx.x * 128;
    int bg = blockIdx.z;
    int tid = threadIdx.x;

    if (blockIdx.x == 0 && bg == 0 && tid < B) {
        float a = 0.f;
#pragma unroll 16
        for (int d = 0; d < DH; d++)
            a = fmaf(bq[h * DH + d], g_K[tid * HDIM + h * DH + d], a);
        g_c[tid * NHEAD + h] = a;
    }

#pragma unroll 8
    for (int d = 0; d < DH; d++)
        Wq_s[d * 128 + tid] = Wq[(h * DH + d) * EMB1 + e0 + tid];

    for (int bb = 0; bb < 4; bb++) {
        int b = bg * 4 + bb;
        __syncthreads();
        if (tid < DH) Ks[tid] = g_K[b * HDIM + h * DH + tid];
        __syncthreads();
        float a = 0.f;
#pragma unroll 16
        for (int d = 0; d < DH; d++)
            a = fmaf(Wq_s[d * 128 + tid], Ks[d], a);
        g_Weff[(b * NHEAD + h) * EMB1 + e0 + tid] = a;
    }
}

// ---------------------------------------------------------------------------
// Kernel 3 (main): EXACT R5 row-pair inner loop at (256,2). Only change:
// balanced pair mapping p = gx + 18*warp + 144k, which puts at most ONE
// heavy (8-pair) warp in each block (uniform 57/56 pairs per block) instead
// of concentrating all heavy warps in blocks gx=0,1.
// ---------------------------------------------------------------------------
__global__ __launch_bounds__(256, 2) void main_kernel(const float* __restrict__ emb1,
                                                      float* __restrict__ out) {
    extern __shared__ float sm[];
    float* Weff_s = sm;                    // 16384 floats
    float* V_s = sm + NHEAD * EMB1;        // 1024 floats
    float* c_s = V_s + HDIM;               // 16 floats

    int b = blockIdx.y;
    int tid = threadIdx.x;

    // Cooperative staging of Weff[b], V[b], c[b]
    {
        const float4* Wg = (const float4*)(g_Weff + (size_t)b * NHEAD * EMB1);
        float4* Ws4 = (float4*)Weff_s;
#pragma unroll
        for (int i = 0; i < NHEAD * EMB1 / 4 / 256; i++)
            Ws4[i * 256 + tid] = Wg[i * 256 + tid];
        const float4* Vg = (const float4*)(g_V + (size_t)b * HDIM);
        if (tid < HDIM / 4) ((float4*)V_s)[tid] = Vg[tid];
        if (tid < NHEAD) c_s[tid] = g_c[b * NHEAD + tid];
    }
    __syncthreads();

    int warp = tid >> 5, lane = tid & 31;
    const ulonglong2* Wsd = (const ulonglong2*)Weff_s;
    const float4* Vs4 = (const float4*)V_s;
    int hi = lane >> 4;
    float c_l = c_s[lane & 15];

    // Balanced mapping: residue = gx + 18*warp (bijection over 144 warps).
    for (int p = blockIdx.x + GRIDX * warp; p < LQ / 2; p += GRIDX * 8) {
        const ulonglong2* x0p = (const ulonglong2*)(emb1 + ((size_t)b * LQ + 2 * p) * EMB1);
        const ulonglong2* x1p = x0p + EMB1 / 4;

        ulonglong2 x0 = __ldg(x0p + lane);
        ulonglong2 x1 = __ldg(x1p + lane);

        unsigned long long acc0[NHEAD], acc1[NHEAD];
#pragma unroll
        for (int h = 0; h < NHEAD; h++) { acc0[h] = 0ull; acc1[h] = 0ull; }

#pragma unroll
        for (int i = 0; i < 8; i++) {
            ulonglong2 x0n, x1n;
            if (i < 7) {                               // prefetch next chunk
                x0n = __ldg(x0p + (i + 1) * 32 + lane);
                x1n = __ldg(x1p + (i + 1) * 32 + lane);
            }
#pragma unroll
            for (int h = 0; h < NHEAD; h++) {
                ulonglong2 w = Wsd[h * 256 + i * 32 + lane];
                fma2(acc0[h], x0.x, w.x);
                fma2(acc0[h], x0.y, w.y);
                fma2(acc1[h], x1.x, w.x);
                fma2(acc1[h], x1.y, w.y);
            }
            if (i < 7) { x0 = x0n; x1 = x1n; }
        }

        // Unpack f32x2 partials, then folded reduction: lane l -> head (l&15).
        float v0[NHEAD], v1[NHEAD];
#pragma unroll
        for (int h = 0; h < NHEAD; h++) {
            v0[h] = unpack_sum(acc0[h]);
            v1[h] = unpack_sum(acc1[h]);
        }
#pragma unroll
        for (int s = 0; s < 4; s++) {
            int o = 1 << s;
            int bit = (lane >> s) & 1;
#pragma unroll
            for (int j = 0; j < (8 >> s); j++) {
                float k0 = bit ? v0[2 * j + 1] : v0[2 * j];
                float s0 = bit ? v0[2 * j] : v0[2 * j + 1];
                v0[j] = k0 + __shfl_xor_sync(0xffffffffu, s0, o);
                float k1 = bit ? v1[2 * j + 1] : v1[2 * j];
                float s1 = bit ? v1[2 * j] : v1[2 * j + 1];
                v1[j] = k1 + __shfl_xor_sync(0xffffffffu, s1, o);
            }
        }
        v0[0] += __shfl_xor_sync(0xffffffffu, v0[0], 16);
        v1[0] += __shfl_xor_sync(0xffffffffu, v1[0], 16);

        float sig0 = __fdividef(1.f, 1.f + __expf(-(v0[0] + c_l)));
        float sig1 = __fdividef(1.f, 1.f + __expf(-(v1[0] + c_l)));

        float4* o0 = (float4*)(out + ((size_t)b * LQ + 2 * p) * EMB1);
        float4* o1 = o0 + EMB1 / 4;
#pragma unroll
        for (int i = 0; i < 8; i++) {
            // float4 (i*32+lane) belongs to head 2i + hi; lane (2i+hi) holds it.
            float s0 = __shfl_sync(0xffffffffu, sig0, 2 * i + hi);
            float s1 = __shfl_sync(0xffffffffu, sig1, 2 * i + hi);
            float4 v = Vs4[i * 32 + lane];
            float4 r0, r1;
            r0.x = s0 * v.x; r0.y = s0 * v.y; r0.z = s0 * v.z; r0.w = s0 * v.w;
            r1.x = s1 * v.x; r1.y = s1 * v.y; r1.z = s1 * v.z; r1.w = s1 * v.w;
            o0[i * 32 + lane] = r0;
            o1[i * 32 + lane] = r1;
        }
    }
}

// ---------------------------------------------------------------------------
extern "C" void kernel_launch(void* const* d_in, const int* in_sizes, int n_in,
                              void* d_out, int out_size) {
    const float* emb1 = (const float*)d_in[0];
    const float* emb2 = (const float*)d_in[1];
    const float* Wq   = (const float*)d_in[2];
    const float* bq   = (const float*)d_in[3];
    const float* Wk   = (const float*)d_in[4];
    const float* bk   = (const float*)d_in[5];
    const float* Wv   = (const float*)d_in[6];
    const float* bv   = (const float*)d_in[7];
    float* out = (float*)d_out;

    kv_kernel<<<HDIM / 2, 256>>>(emb2, Wk, bk, Wv, bv);
    weff_kernel<<<dim3(EMB1 / 128, NHEAD, 4), 128>>>(Wq, bq);

    int smem = (NHEAD * EMB1 + HDIM + NHEAD) * (int)sizeof(float);  // ~69.7 KB
    static bool attr_set = false;
    if (!attr_set) {
        cudaFuncSetAttribute(main_kernel, cudaFuncAttributeMaxDynamicSharedMemorySize, smem);
        attr_set = true;
    }
    main_kernel<<<dim3(GRIDX, B), 256, smem>>>(emb1, out);
}